// round 17
// baseline (speedup 1.0000x reference)
#include <cuda_runtime.h>
#include <cstdint>

constexpr int BATCH = 128;
constexpr int NODES = 8192;
constexpr int NI    = 6;
constexpr int NE    = 64;
constexpr int BB    = 16;     // batches per CTA column
constexpr int TPB   = 64;     // 64 nodes per CTA, full node per thread
constexpr int XSTRIDE = NODES * NI;        // floats between consecutive batches
constexpr int PAIRS  = BB / 2;             // 8 pairs of batches
constexpr int RING   = 4;                  // pair slots resident in smem
constexpr int PAIR_FLOATS = 2 * TPB * NI;  // 768 floats = 3072 B per pair

using u64 = unsigned long long;

__device__ __forceinline__ u64 pk2(float lo, float hi) {
    u64 r; asm("mov.b64 %0, {%1, %2};" : "=l"(r) : "f"(lo), "f"(hi)); return r;
}
__device__ __forceinline__ void upk2(u64 v, float& lo, float& hi) {
    asm("mov.b64 {%0, %1}, %2;" : "=f"(lo), "=f"(hi) : "l"(v));
}
__device__ __forceinline__ u64 fma2(u64 a, u64 b, u64 c) {
    u64 d; asm("fma.rn.f32x2 %0, %1, %2, %3;" : "=l"(d) : "l"(a), "l"(b), "l"(c)); return d;
}
__device__ __forceinline__ u64 sub2(u64 a, u64 b) {
    u64 d; asm("sub.rn.f32x2 %0, %1, %2;" : "=l"(d) : "l"(a), "l"(b)); return d;
}
__device__ __forceinline__ void cpa16(uint32_t dst, const void* src) {
    asm volatile("cp.async.cg.shared.global [%0], [%1], 16;" :: "r"(dst), "l"(src) : "memory");
}
__device__ __forceinline__ void cpa_commit() {
    asm volatile("cp.async.commit_group;" ::: "memory");
}
template<int N>
__device__ __forceinline__ void cpa_wait() {
    asm volatile("cp.async.wait_group %0;" :: "n"(N) : "memory");
}

// out[b,n] = 6-D multilinear interp of tables[n,:] at clip(x[b,n,:], 0, 1).
// Bits 0,1 folded into per-node quad coefficients (a + x0 b + x1 c + x0x1 d),
// bits 2..4 packed difference-form lerps, bit 5 packed across f32x2 lanes.
// R17: x streamed by cp.async (LDGSTS) into a 4-pair smem ring -- the register
// double-buffer of R11..R15 only sustained ~1.5 outstanding loads/thread
// (back-computed from 2.5TB/s @ ~600cyc); the async engine holds 9-12 16B
// copies/thread in flight and the mainloop reads x via 29-cyc LDS instead of
// DRAM-latency LDG.
__global__ void __launch_bounds__(TPB, 7)
lut_kernel(const float* __restrict__ x,
           const float* __restrict__ tables,
           float* __restrict__ out)
{
    __shared__ float tbl[TPB * NE];               // 16 KB
    __shared__ float xr[RING * PAIR_FLOATS];      // 12 KB ring (4 pairs)

    const int tid = threadIdx.x;
    const int n0  = blockIdx.x * TPB;             // first node of this block
    const int b0  = blockIdx.y * BB;              // first batch of this block

    const uint32_t xr0 = (uint32_t)__cvta_generic_to_shared(xr);
    // gmem base of batch b0 for this block's nodes (float4-aligned: n0*NI*4B % 16 == 0)
    const float* xg = x + ((size_t)b0 * NODES + n0) * NI;

    // issue async x copies for pair p into ring slot s. Pair region = batches
    // (2p, 2p+1) = 192 float4; thread covers f4 indices tid, tid+64, tid+128.
    auto issue_pair = [&](int p, int s) {
        const float* bsrc0 = xg + (size_t)(2 * p)     * XSTRIDE;  // batch 2p
        const float* bsrc1 = xg + (size_t)(2 * p + 1) * XSTRIDE;  // batch 2p+1
        uint32_t d = xr0 + (uint32_t)(s * PAIR_FLOATS * 4);
        // f4 idx tid  (< 96 -> batch 2p)
        cpa16(d + tid * 16u, bsrc0 + tid * 4);
        // f4 idx tid+64 (batch 2p if tid<32, else batch 2p+1 at idx tid-32)
        const float* m = (tid < 32) ? (bsrc0 + (tid + 64) * 4)
                                    : (bsrc1 + (tid - 32) * 4);
        cpa16(d + (tid + 64) * 16u, m);
        // f4 idx tid+128 (batch 2p+1 at idx tid+32)
        cpa16(d + (tid + 128) * 16u, bsrc1 + (tid + 32) * 4);
        cpa_commit();
    };

    // ---- fill the ring: pairs 0..3 in flight before anything else ----
    #pragma unroll
    for (int p = 0; p < RING; p++) issue_pair(p, p);

    // ---- stage this block's 16KB table chunk: coalesced LDG -> +2*row-rotated STS.64 ----
    {
        const float4* tg = (const float4*)(tables + (size_t)n0 * NE);
        #pragma unroll
        for (int j = 0; j < (TPB * NE / 4) / TPB; j++) {    // 16 float4 per thread
            int i = tid + j * TPB;                          // coalesced gmem index
            float4 v = tg[i];
            int r  = i >> 4;                                // dest row
            int c0 = (i & 15) * 4;                          // first word (even)
            float* row = tbl + r * NE;
            int w0 = (c0     + 2 * r) & (NE - 1);           // even -> 8B aligned
            int w1 = (c0 + 2 + 2 * r) & (NE - 1);
            *(float2*)(row + w0) = make_float2(v.x, v.y);
            *(float2*)(row + w1) = make_float2(v.z, v.w);
        }
    }
    __syncthreads();

    // ---- per-node packed quad coefficients over bits 0,1 (pairing = bit 5) ----
    // quad m covers entries 4m..4m+3 (lane lo) and 4m+32..4m+35 (lane hi):
    //   val = a + x0*b + x1*c + x0*x1*d
    u64 Aq[8], Bq[8], Cq[8], Dq[8];
    {
        const float* tr = tbl + (size_t)tid * NE;
        const int rot = (2 * tid) & (NE - 1);               // even: float2 pairs intact
        #pragma unroll
        for (int m = 0; m < 8; m++) {
            float2 l01 = *(const float2*)(tr + ((4*m      + rot) & (NE - 1)));
            float2 l23 = *(const float2*)(tr + ((4*m + 2  + rot) & (NE - 1)));
            float2 h01 = *(const float2*)(tr + ((4*m + 32 + rot) & (NE - 1)));
            float2 h23 = *(const float2*)(tr + ((4*m + 34 + rot) & (NE - 1)));
            float lb = l01.y - l01.x, hb = h01.y - h01.x;
            Aq[m] = pk2(l01.x, h01.x);
            Bq[m] = pk2(lb, hb);
            Cq[m] = pk2(l23.x - l01.x, h23.x - h01.x);
            Dq[m] = pk2((l23.y - l23.x) - lb, (h23.y - h23.x) - hb);
        }
    }

    auto fold = [&](float2 q0, float2 q1, float2 q2) -> float {
        float c0 = __saturatef(q0.x), c1 = __saturatef(q0.y);
        float c2 = __saturatef(q1.x), c3 = __saturatef(q1.y);
        float c4 = __saturatef(q2.x), c5 = __saturatef(q2.y);
        float c01 = c0 * c1;
        u64 x0  = pk2(c0,  c0), x1 = pk2(c1, c1), x01 = pk2(c01, c01);
        u64 x2  = pk2(c2,  c2), x3 = pk2(c3, c3), x4  = pk2(c4, c4);

        u64 W[8];
        #pragma unroll
        for (int m = 0; m < 8; m++)
            W[m] = fma2(x01, Dq[m], fma2(x1, Cq[m], fma2(x0, Bq[m], Aq[m])));
        #pragma unroll
        for (int m = 0; m < 4; m++) W[m] = fma2(x2, sub2(W[2*m+1], W[2*m]), W[2*m]);
        #pragma unroll
        for (int m = 0; m < 2; m++) W[m] = fma2(x3, sub2(W[2*m+1], W[2*m]), W[2*m]);
        W[0] = fma2(x4, sub2(W[1], W[0]), W[0]);

        float lo, hi; upk2(W[0], lo, hi);
        return fmaf(c5, hi - lo, lo);
    };

    float* op = out + (size_t)b0 * NODES + n0 + tid;

    // ---- mainloop over 8 pairs (fully unrolled; wait counts compile-time) ----
    #pragma unroll
    for (int p = 0; p < PAIRS; p++) {
        // own-group completion: committed = min(4+p, 8); need groups <= p done
        if      (p <= 4) cpa_wait<3>();
        else if (p == 5) cpa_wait<2>();
        else if (p == 6) cpa_wait<1>();
        else             cpa_wait<0>();
        __syncthreads();                         // all threads' copies visible

        const int s = p & (RING - 1);
        const float* xp = xr + s * PAIR_FLOATS + tid * NI;

        // batch 2p
        float2 a0 = *(const float2*)(xp + 0);
        float2 a1 = *(const float2*)(xp + 2);
        float2 a2 = *(const float2*)(xp + 4);
        // batch 2p+1 (second half of pair region)
        float2 b0f = *(const float2*)(xp + TPB * NI + 0);
        float2 b1f = *(const float2*)(xp + TPB * NI + 2);
        float2 b2f = *(const float2*)(xp + TPB * NI + 4);

        op[(2 * p)     * NODES] = fold(a0, a1, a2);
        op[(2 * p + 1) * NODES] = fold(b0f, b1f, b2f);

        __syncthreads();                         // all reads of slot s retired
        if (p < PAIRS - RING) issue_pair(p + RING, s);
    }
}

extern "C" void kernel_launch(void* const* d_in, const int* in_sizes, int n_in,
                              void* d_out, int out_size)
{
    const float* x;
    const float* tables;
    if (in_sizes[0] == BATCH * NODES * NI) {
        x = (const float*)d_in[0]; tables = (const float*)d_in[1];
    } else {
        x = (const float*)d_in[1]; tables = (const float*)d_in[0];
    }
    dim3 grid(NODES / TPB, BATCH / BB);     // 128 x 8 = 1024 CTAs
    lut_kernel<<<grid, TPB>>>(x, tables, (float*)d_out);
}